// round 1
// baseline (speedup 1.0000x reference)
#include <cuda_runtime.h>
#include <cstdint>

// ---------------- problem constants ----------------
#define BB   8
#define NN   2048
#define DIN  2
#define DS   32
#define DO   32
#define GE   8
#define HID  32
#define DCAT 66            // DIN + 2*DS
#define DGI  74            // DIN + 2*DS + GE
#define DBASIS 396         // 2 supports * 3 cheb * 66
#define GOUT 96            // 3*DO

#define TOTN (BB*NN)       // 16384
#define SZ66 ((size_t)TOTN*DCAT)   // 1,081,344
#define SZ32 ((size_t)TOTN*DO)     // 524,288

// scratch: X, C, T0..T3 (each SZ66), state, r (each SZ32)
__device__ float g_scratch[6*1081344 + 2*524288];

// offsets (floats)
#define OFF_X  ((size_t)0)
#define OFF_C  (SZ66)
#define OFF_T0 (2*SZ66)
#define OFF_T1 (3*SZ66)
#define OFF_T2 (4*SZ66)
#define OFF_T3 (5*SZ66)
#define OFF_ST (6*SZ66)
#define OFF_R  (6*SZ66 + SZ32)

__device__ __forceinline__ float sigmoidf_(float x) {
    return 1.0f / (1.0f + __expf(-x));
}

// ---------------------------------------------------------------------------
// Kernel 1: prep — gate MLP -> mr -> state ; write X = [xt, s1, s2]
// block: 256 threads = 8 nodes x 32 channels
// ---------------------------------------------------------------------------
__global__ void prep_kernel(const float* __restrict__ xt,
                            const float* __restrict__ s1,
                            const float* __restrict__ s2,
                            const float* __restrict__ ge,
                            const float* __restrict__ mlp_w,   // (74,32)
                            const float* __restrict__ mlp_b,
                            float* __restrict__ gX,
                            float* __restrict__ gstate)
{
    __shared__ float sg[8][DGI];
    const int t  = threadIdx.x;
    const int nb = blockIdx.x * 8;

    for (int idx = t; idx < 8 * DGI; idx += 256) {
        int nn = idx / DGI, i = idx % DGI;
        int node = nb + nn;
        float v;
        if (i < DIN)            v = xt[node*DIN + i];
        else if (i < DIN+DS)    v = s1[node*DS + (i-DIN)];
        else if (i < DIN+2*DS)  v = s2[node*DS + (i-DIN-DS)];
        else                    v = ge[node*GE + (i-DIN-2*DS)];
        sg[nn][i] = v;
    }
    __syncthreads();

    // write X (first 66 entries of gate_in)
    for (int idx = t; idx < 8 * DCAT; idx += 256) {
        int nn = idx / DCAT, i = idx % DCAT;
        gX[(size_t)(nb+nn)*DCAT + i] = sg[nn][i];
    }

    const int n = t >> 5;       // node-in-block
    const int c = t & 31;       // channel
    float acc = mlp_b[c];
#pragma unroll 8
    for (int i = 0; i < DGI; i++)
        acc = fmaf(sg[n][i], mlp_w[i*DO + c], acc);
    float mr = sigmoidf_(acc);

    int node = nb + n;
    float a = s1[node*DS + c];
    float b = s2[node*DS + c];
    gstate[node*DS + c] = mr*a + (1.0f - mr)*b;
}

// ---------------------------------------------------------------------------
// Kernel 2: batched skinny GEMM
// Out[b,n,c] = alpha * sum_m A[b,n,m]*Xin[b,m,c] + beta * Base[b,n,c]
// A: (B, N, N), Xin/Base/Out: (B*N, 66)
// Tile: BM=64 rows, all 66 cols, BK=64.  256 threads, 4x5 micro-tile.
// grid: (N/64, B)
// ---------------------------------------------------------------------------
#define BM 64
#define BK 64
__global__ __launch_bounds__(256) void gemm_ax(const float* __restrict__ A,
                        const float* __restrict__ Xin,
                        const float* __restrict__ Base,
                        float* __restrict__ Out,
                        float alpha, float beta)
{
    __shared__ float sA[BK][BM + 4];   // k-major, padded so [k][ty*4] is 16B aligned (stride 68)
    __shared__ float sX[BK][80];       // cols 66..79 zeroed -> branch-free 5th col

    const int t    = threadIdx.x;
    const int b    = blockIdx.y;
    const int row0 = blockIdx.x * BM;

    const float* Ab = A + ((size_t)b * NN + row0) * NN;
    const float* Xb = Xin + (size_t)b * NN * DCAT;

    const int ty = t >> 4;   // 0..15 (4 rows each)
    const int tx = t & 15;   // 0..15 (cols tx + 16j)

    float acc[4][5];
#pragma unroll
    for (int i = 0; i < 4; i++)
#pragma unroll
        for (int j = 0; j < 5; j++) acc[i][j] = 0.0f;

    const int lr = t >> 4;       // A-load: row group 0..15
    const int k4 = t & 15;       // A-load: float4 index along k

    for (int k0 = 0; k0 < NN; k0 += BK) {
        // --- load A tile (64 rows x 64 k), store k-major ---
#pragma unroll
        for (int rr = 0; rr < 4; rr++) {
            int r = lr + 16*rr;
            float4 v = *(const float4*)(Ab + (size_t)r*NN + k0 + k4*4);
            sA[k4*4+0][r] = v.x;
            sA[k4*4+1][r] = v.y;
            sA[k4*4+2][r] = v.z;
            sA[k4*4+3][r] = v.w;
        }
        // --- load X tile (64 k x 66 cols, pad to 80) ---
        for (int idx = t; idx < BK*80; idx += 256) {
            int kk = idx / 80, cc = idx - kk*80;
            sX[kk][cc] = (cc < DCAT) ? Xb[(size_t)(k0+kk)*DCAT + cc] : 0.0f;
        }
        __syncthreads();

#pragma unroll 16
        for (int kk = 0; kk < BK; kk++) {
            float4 a4 = *(const float4*)&sA[kk][ty*4];
            float ra[4] = {a4.x, a4.y, a4.z, a4.w};
            float rx[5];
#pragma unroll
            for (int j = 0; j < 5; j++) rx[j] = sX[kk][tx + 16*j];
#pragma unroll
            for (int i = 0; i < 4; i++)
#pragma unroll
                for (int j = 0; j < 5; j++)
                    acc[i][j] = fmaf(ra[i], rx[j], acc[i][j]);
        }
        __syncthreads();
    }

    // --- epilogue ---
#pragma unroll
    for (int i = 0; i < 4; i++) {
        int row = row0 + ty*4 + i;
        size_t base = ((size_t)b * NN + row) * DCAT;
#pragma unroll
        for (int j = 0; j < 5; j++) {
            int cc = tx + 16*j;
            if (cc < DCAT) {
                float v = alpha * acc[i][j];
                if (Base) v = fmaf(beta, Base[base + cc], v);
                Out[base + cc] = v;
            }
        }
    }
}

// ---------------------------------------------------------------------------
// Kernel 3: gate combine -> zz_r = sigmoid(basis @ gate_w + b)
// emits candidate = [xt, z1*s1, z2*s2] and r
// block: 96 threads (one output channel each), 8 nodes per block
// ---------------------------------------------------------------------------
__global__ void combine_gate(const float* __restrict__ X,
                             const float* __restrict__ T0,
                             const float* __restrict__ T1,
                             const float* __restrict__ T2,
                             const float* __restrict__ T3,
                             const float* __restrict__ gate_w,  // (396,96)
                             const float* __restrict__ gate_b,
                             const float* __restrict__ xt,
                             const float* __restrict__ s1,
                             const float* __restrict__ s2,
                             float* __restrict__ cand,
                             float* __restrict__ r_out)
{
    __shared__ float s[8][DBASIS];
    const int t  = threadIdx.x;     // 0..95
    const int nb = blockIdx.x * 8;

    for (int idx = t; idx < 8*DBASIS; idx += 96) {
        int n = idx / DBASIS, i = idx - n*DBASIS;
        int term = i / DCAT, w = i - term*DCAT;
        const float* src;
        switch (term) {
            case 0: src = X;  break;
            case 1: src = T0; break;
            case 2: src = T1; break;
            case 3: src = X;  break;
            case 4: src = T2; break;
            default: src = T3; break;
        }
        s[n][i] = src[(size_t)(nb+n)*DCAT + w];
    }
    __syncthreads();

    const int c = t;
    float acc[8];
    float bc = gate_b[c];
#pragma unroll
    for (int n = 0; n < 8; n++) acc[n] = bc;

    for (int i = 0; i < DBASIS; i++) {
        float w = gate_w[i*GOUT + c];
#pragma unroll
        for (int n = 0; n < 8; n++)
            acc[n] = fmaf(s[n][i], w, acc[n]);
    }

#pragma unroll
    for (int n = 0; n < 8; n++) {
        int node = nb + n;
        float v = sigmoidf_(acc[n]);
        if (c < DO) {
            cand[(size_t)node*DCAT + DIN + c] = v * s1[node*DS + c];
        } else if (c < 2*DO) {
            int cc = c - DO;
            cand[(size_t)node*DCAT + DIN + DS + cc] = v * s2[node*DS + cc];
        } else {
            r_out[node*DO + (c - 2*DO)] = v;
        }
        if (c < DIN)
            cand[(size_t)node*DCAT + c] = xt[node*DIN + c];
    }
}

// ---------------------------------------------------------------------------
// Kernel 4: final — hc = tanh(basis @ upd_w + b); h = r*state + (1-r)*hc;
// transnext = h @ hop_w + hop_b.  block: 256 = 8 nodes x 32 channels
// ---------------------------------------------------------------------------
__global__ void final_kernel(const float* __restrict__ C,
                             const float* __restrict__ T0,
                             const float* __restrict__ T1,
                             const float* __restrict__ T2,
                             const float* __restrict__ T3,
                             const float* __restrict__ upd_w,   // (396,32)
                             const float* __restrict__ upd_b,
                             const float* __restrict__ hop_w,   // (32,32)
                             const float* __restrict__ hop_b,
                             const float* __restrict__ g_r,
                             const float* __restrict__ g_state,
                             float* __restrict__ out)
{
    __shared__ float s[8][DBASIS];
    __shared__ float hsh[8][DO];
    const int t  = threadIdx.x;
    const int nb = blockIdx.x * 8;

    for (int idx = t; idx < 8*DBASIS; idx += 256) {
        int n = idx / DBASIS, i = idx - n*DBASIS;
        int term = i / DCAT, w = i - term*DCAT;
        const float* src;
        switch (term) {
            case 0: src = C;  break;
            case 1: src = T0; break;
            case 2: src = T1; break;
            case 3: src = C;  break;
            case 4: src = T2; break;
            default: src = T3; break;
        }
        s[n][i] = src[(size_t)(nb+n)*DCAT + w];
    }
    __syncthreads();

    const int n = t >> 5;
    const int c = t & 31;
    const int node = nb + n;

    float acc = upd_b[c];
    for (int i = 0; i < DBASIS; i++)
        acc = fmaf(s[n][i], upd_w[i*DO + c], acc);

    float hc = tanhf(acc);
    float r  = g_r[node*DO + c];
    float st = g_state[node*DS + c];
    float h  = r*st + (1.0f - r)*hc;

    out[(size_t)node*DO + c] = h;
    hsh[n][c] = h;
    __syncthreads();

    float a2 = hop_b[c];
#pragma unroll
    for (int i = 0; i < HID; i++)
        a2 = fmaf(hsh[n][i], hop_w[i*HID + c], a2);
    out[(size_t)TOTN*DO + (size_t)node*HID + c] = a2;
}

// ---------------------------------------------------------------------------
// launch
// ---------------------------------------------------------------------------
extern "C" void kernel_launch(void* const* d_in, const int* in_sizes, int n_in,
                              void* d_out, int out_size)
{
    const float* xt     = (const float*)d_in[0];
    const float* s1     = (const float*)d_in[1];
    const float* s2     = (const float*)d_in[2];
    const float* ge     = (const float*)d_in[3];
    const float* sup    = (const float*)d_in[4];
    const float* mlp_w  = (const float*)d_in[5];
    const float* mlp_b  = (const float*)d_in[6];
    const float* gate_w = (const float*)d_in[7];
    const float* gate_b = (const float*)d_in[8];
    const float* upd_w  = (const float*)d_in[9];
    const float* upd_b  = (const float*)d_in[10];
    const float* hop_w  = (const float*)d_in[11];
    const float* hop_b  = (const float*)d_in[12];
    float* out = (float*)d_out;

    float* scr = nullptr;
    cudaGetSymbolAddress((void**)&scr, g_scratch);

    float* gX  = scr + OFF_X;
    float* gC  = scr + OFF_C;
    float* gT0 = scr + OFF_T0;
    float* gT1 = scr + OFF_T1;
    float* gT2 = scr + OFF_T2;
    float* gT3 = scr + OFF_T3;
    float* gST = scr + OFF_ST;
    float* gR  = scr + OFF_R;

    const float* A0 = sup;
    const float* A1 = sup + (size_t)BB * NN * NN;

    dim3 ggrid(NN / BM, BB);

    // 1. prep: mr/state + X
    prep_kernel<<<TOTN/8, 256>>>(xt, s1, s2, ge, mlp_w, mlp_b, gX, gST);

    // 2. Chebyshev terms on X
    gemm_ax<<<ggrid, 256>>>(A0, gX,  nullptr, gT0, 1.0f,  0.0f);
    gemm_ax<<<ggrid, 256>>>(A0, gT0, gX,      gT1, 2.0f, -1.0f);
    gemm_ax<<<ggrid, 256>>>(A1, gX,  nullptr, gT2, 1.0f,  0.0f);
    gemm_ax<<<ggrid, 256>>>(A1, gT2, gX,      gT3, 2.0f, -1.0f);

    // 3. gate combine -> candidate, r
    combine_gate<<<TOTN/8, 96>>>(gX, gT0, gT1, gT2, gT3,
                                 gate_w, gate_b, xt, s1, s2, gC, gR);

    // 4. Chebyshev terms on candidate
    gemm_ax<<<ggrid, 256>>>(A0, gC,  nullptr, gT0, 1.0f,  0.0f);
    gemm_ax<<<ggrid, 256>>>(A0, gT0, gC,      gT1, 2.0f, -1.0f);
    gemm_ax<<<ggrid, 256>>>(A1, gC,  nullptr, gT2, 1.0f,  0.0f);
    gemm_ax<<<ggrid, 256>>>(A1, gT2, gC,      gT3, 2.0f, -1.0f);

    // 5. final: hc, h, transnext
    final_kernel<<<TOTN/8, 256>>>(gC, gT0, gT1, gT2, gT3,
                                  upd_w, upd_b, hop_w, hop_b,
                                  gR, gST, out);
}

// round 3
// speedup vs baseline: 2.4860x; 2.4860x over previous
#include <cuda_runtime.h>
#include <cuda_bf16.h>
#include <cstdint>

// ---------------- problem constants ----------------
#define BB   8
#define NN   2048
#define DIN  2
#define DS   32
#define DO   32
#define GE   8
#define HID  32
#define DCAT 66            // DIN + 2*DS
#define DGI  74            // DIN + 2*DS + GE
#define DBASIS 396         // 2 supports * 3 cheb * 66
#define GOUT 96            // 3*DO

#define TOTN (BB*NN)       // 16384
#define SZ66 ((size_t)TOTN*DCAT)
#define SZ32 ((size_t)TOTN*DO)

__device__ float g_scratch[6*1081344 + 2*524288];

#define OFF_X  ((size_t)0)
#define OFF_C  (SZ66)
#define OFF_T0 (2*SZ66)
#define OFF_T1 (3*SZ66)
#define OFF_T2 (4*SZ66)
#define OFF_T3 (5*SZ66)
#define OFF_ST (6*SZ66)
#define OFF_R  (6*SZ66 + SZ32)

__device__ __forceinline__ float sigmoidf_(float x) {
    return 1.0f / (1.0f + __expf(-x));
}

// ---------------------------------------------------------------------------
// mma / ldmatrix helpers
// ---------------------------------------------------------------------------
__device__ __forceinline__ void ldsm4(uint32_t r[4], const void* p) {
    uint32_t a = (uint32_t)__cvta_generic_to_shared(p);
    asm volatile("ldmatrix.sync.aligned.m8n8.x4.shared.b16 {%0,%1,%2,%3},[%4];"
        : "=r"(r[0]), "=r"(r[1]), "=r"(r[2]), "=r"(r[3]) : "r"(a));
}
__device__ __forceinline__ void ldsm4t(uint32_t& r0, uint32_t& r1, uint32_t& r2, uint32_t& r3,
                                       const void* p) {
    uint32_t a = (uint32_t)__cvta_generic_to_shared(p);
    asm volatile("ldmatrix.sync.aligned.m8n8.x4.trans.shared.b16 {%0,%1,%2,%3},[%4];"
        : "=r"(r0), "=r"(r1), "=r"(r2), "=r"(r3) : "r"(a));
}
__device__ __forceinline__ void ldsm2t(uint32_t r[2], const void* p) {
    uint32_t a = (uint32_t)__cvta_generic_to_shared(p);
    asm volatile("ldmatrix.sync.aligned.m8n8.x2.trans.shared.b16 {%0,%1},[%2];"
        : "=r"(r[0]), "=r"(r[1]) : "r"(a));
}
__device__ __forceinline__ void mma_bf16(float c[4], const uint32_t a[4], const uint32_t b[2]) {
    asm volatile(
        "mma.sync.aligned.m16n8k16.row.col.f32.bf16.bf16.f32 "
        "{%0,%1,%2,%3},{%4,%5,%6,%7},{%8,%9},{%0,%1,%2,%3};"
        : "+f"(c[0]), "+f"(c[1]), "+f"(c[2]), "+f"(c[3])
        : "r"(a[0]), "r"(a[1]), "r"(a[2]), "r"(a[3]), "r"(b[0]), "r"(b[1]));
}

// ---------------------------------------------------------------------------
// Kernel 1: prep — gate MLP -> mr -> state ; write X = [xt, s1, s2]
// ---------------------------------------------------------------------------
__global__ void prep_kernel(const float* __restrict__ xt,
                            const float* __restrict__ s1,
                            const float* __restrict__ s2,
                            const float* __restrict__ ge,
                            const float* __restrict__ mlp_w,
                            const float* __restrict__ mlp_b,
                            float* __restrict__ gX,
                            float* __restrict__ gstate)
{
    __shared__ float sg[8][DGI];
    const int t  = threadIdx.x;
    const int nb = blockIdx.x * 8;

    for (int idx = t; idx < 8 * DGI; idx += 256) {
        int nn = idx / DGI, i = idx % DGI;
        int node = nb + nn;
        float v;
        if (i < DIN)            v = xt[node*DIN + i];
        else if (i < DIN+DS)    v = s1[node*DS + (i-DIN)];
        else if (i < DIN+2*DS)  v = s2[node*DS + (i-DIN-DS)];
        else                    v = ge[node*GE + (i-DIN-2*DS)];
        sg[nn][i] = v;
    }
    __syncthreads();

    for (int idx = t; idx < 8 * DCAT; idx += 256) {
        int nn = idx / DCAT, i = idx % DCAT;
        gX[(size_t)(nb+nn)*DCAT + i] = sg[nn][i];
    }

    const int n = t >> 5;
    const int c = t & 31;
    float acc = mlp_b[c];
#pragma unroll 8
    for (int i = 0; i < DGI; i++)
        acc = fmaf(sg[n][i], mlp_w[i*DO + c], acc);
    float mr = sigmoidf_(acc);

    int node = nb + n;
    float a = s1[node*DS + c];
    float b = s2[node*DS + c];
    gstate[node*DS + c] = mr*a + (1.0f - mr)*b;
}

// ---------------------------------------------------------------------------
// Kernel 2: tensor-core batched skinny GEMM (bf16 3-product split, fp32 acc)
// Out[b,n,c] = alpha * sum_m A[b,n,m]*Xin[b,m,c] + beta * Base[b,n,c]
// CTA tile: 64 rows x 80 cols (66 used), K-chunk 32, 128 threads (4 warps 2x2)
// warp tile: 32 x 40 = 2 m16 x 5 n8 frags, 3 mma per frag pair
// ---------------------------------------------------------------------------
__global__ __launch_bounds__(128) void gemm_tc(const float* __restrict__ A,
                                               const float* __restrict__ Xin,
                                               const float* __restrict__ Base,
                                               float* __restrict__ Out,
                                               float alpha, float beta)
{
    // A tiles: row-major [m][k], pitch 40 bf16 (80B: coprime-8 16B-groups for LDSM)
    // B tiles: row-major [k][n], pitch 88 bf16 (176B: coprime-8)
    __shared__ __nv_bfloat16 sAh[2][64][40];
    __shared__ __nv_bfloat16 sAl[2][64][40];
    __shared__ __nv_bfloat16 sBh[2][32][88];
    __shared__ __nv_bfloat16 sBl[2][32][88];

    const int t    = threadIdx.x;
    const int b    = blockIdx.y;
    const int row0 = blockIdx.x * 64;

    const float* Ab = A + ((size_t)b * NN + row0) * NN;
    const float* Xb = Xin + (size_t)b * NN * DCAT;

    // zero the B pad columns (66..87) once; never rewritten
    for (int idx = t; idx < 2*32*22; idx += 128) {
        int bb = idx / (32*22);
        int rem = idx - bb*(32*22);
        int kk = rem / 22, cc = 66 + rem % 22;
        sBh[bb][kk][cc] = __float2bfloat16(0.0f);
        sBl[bb][kk][cc] = __float2bfloat16(0.0f);
    }

    const int lane = t & 31;
    const int wid  = t >> 5;
    const int wm   = wid >> 1;          // 0..1 (M)
    const int wn   = wid & 1;           // 0..1 (N)

    // shared ldmatrix lane-address components
    const int l_r = (lane & 7) + ((lane >> 3) & 1) * 8;  // row within 16
    const int l_c = (lane >> 4) * 8;                     // 0 or 8

    float acc[2][5][4];
#pragma unroll
    for (int mi = 0; mi < 2; mi++)
#pragma unroll
        for (int j = 0; j < 5; j++)
#pragma unroll
            for (int q = 0; q < 4; q++) acc[mi][j][q] = 0.0f;

    // staging registers
    float4 areg[4];
    float2 xreg[9];
    const int ar = t >> 1;              // A row 0..63
    const int akh = (t & 1) * 16;       // A k-half

    auto LOADR = [&](int k0) {
#pragma unroll
        for (int i = 0; i < 4; i++)
            areg[i] = *(const float4*)(Ab + (size_t)ar*NN + k0 + akh + 4*i);
#pragma unroll
        for (int i = 0; i < 9; i++) {
            int idx = t + 128*i;
            if (idx < 1056) {
                int k = idx / 33, p = idx - 33*k;
                xreg[i] = *(const float2*)(Xb + (size_t)(k0 + k)*DCAT + 2*p);
            }
        }
    };
    auto STORE = [&](int buf) {
#pragma unroll
        for (int i = 0; i < 4; i++) {
            float4 v = areg[i];
            __nv_bfloat16 hx = __float2bfloat16(v.x);
            __nv_bfloat16 hy = __float2bfloat16(v.y);
            __nv_bfloat16 hz = __float2bfloat16(v.z);
            __nv_bfloat16 hw = __float2bfloat16(v.w);
            *(__nv_bfloat162*)&sAh[buf][ar][akh + 4*i]     = __halves2bfloat162(hx, hy);
            *(__nv_bfloat162*)&sAh[buf][ar][akh + 4*i + 2] = __halves2bfloat162(hz, hw);
            __nv_bfloat16 lx = __float2bfloat16(v.x - __bfloat162float(hx));
            __nv_bfloat16 ly = __float2bfloat16(v.y - __bfloat162float(hy));
            __nv_bfloat16 lz = __float2bfloat16(v.z - __bfloat162float(hz));
            __nv_bfloat16 lw = __float2bfloat16(v.w - __bfloat162float(hw));
            *(__nv_bfloat162*)&sAl[buf][ar][akh + 4*i]     = __halves2bfloat162(lx, ly);
            *(__nv_bfloat162*)&sAl[buf][ar][akh + 4*i + 2] = __halves2bfloat162(lz, lw);
        }
#pragma unroll
        for (int i = 0; i < 9; i++) {
            int idx = t + 128*i;
            if (idx < 1056) {
                int k = idx / 33, p = idx - 33*k;
                float2 v = xreg[i];
                __nv_bfloat16 hx = __float2bfloat16(v.x);
                __nv_bfloat16 hy = __float2bfloat16(v.y);
                *(__nv_bfloat162*)&sBh[buf][k][2*p] = __halves2bfloat162(hx, hy);
                __nv_bfloat16 lx = __float2bfloat16(v.x - __bfloat162float(hx));
                __nv_bfloat16 ly = __float2bfloat16(v.y - __bfloat162float(hy));
                *(__nv_bfloat162*)&sBl[buf][k][2*p] = __halves2bfloat162(lx, ly);
            }
        }
    };
    auto MMA = [&](int buf) {
#pragma unroll
        for (int kk = 0; kk < 32; kk += 16) {
            uint32_t ah[2][4], al[2][4];
#pragma unroll
            for (int mi = 0; mi < 2; mi++) {
                ldsm4(ah[mi], &sAh[buf][wm*32 + mi*16 + l_r][kk + l_c]);
                ldsm4(al[mi], &sAl[buf][wm*32 + mi*16 + l_r][kk + l_c]);
            }
            uint32_t bh[5][2], bl[5][2];
            ldsm4t(bh[0][0], bh[0][1], bh[1][0], bh[1][1], &sBh[buf][kk + l_r][wn*40 + 0  + l_c]);
            ldsm4t(bh[2][0], bh[2][1], bh[3][0], bh[3][1], &sBh[buf][kk + l_r][wn*40 + 16 + l_c]);
            ldsm2t(bh[4], &sBh[buf][kk + l_r][wn*40 + 32]);
            ldsm4t(bl[0][0], bl[0][1], bl[1][0], bl[1][1], &sBl[buf][kk + l_r][wn*40 + 0  + l_c]);
            ldsm4t(bl[2][0], bl[2][1], bl[3][0], bl[3][1], &sBl[buf][kk + l_r][wn*40 + 16 + l_c]);
            ldsm2t(bl[4], &sBl[buf][kk + l_r][wn*40 + 32]);
#pragma unroll
            for (int mi = 0; mi < 2; mi++)
#pragma unroll
                for (int j = 0; j < 5; j++) {
                    mma_bf16(acc[mi][j], ah[mi], bh[j]);
                    mma_bf16(acc[mi][j], al[mi], bh[j]);
                    mma_bf16(acc[mi][j], ah[mi], bl[j]);
                }
        }
    };

    // pipeline: prologue
    LOADR(0);
    STORE(0);
    __syncthreads();

    for (int c = 0; c < NN/32; c++) {
        int buf = c & 1;
        if (c < NN/32 - 1) LOADR((c + 1) * 32);
        MMA(buf);
        if (c < NN/32 - 1) STORE(buf ^ 1);
        __syncthreads();
    }

    // epilogue
    const int ro = lane >> 2;
    const int co = (lane & 3) * 2;
#pragma unroll
    for (int mi = 0; mi < 2; mi++) {
#pragma unroll
        for (int j = 0; j < 5; j++) {
            int col = wn*40 + j*8 + co;
            if (col < DCAT) {
#pragma unroll
                for (int h = 0; h < 2; h++) {
                    int row = row0 + wm*32 + mi*16 + ro + h*8;
                    size_t o = ((size_t)b * NN + row) * DCAT + col;
                    float2 v;
                    v.x = alpha * acc[mi][j][h*2 + 0];
                    v.y = alpha * acc[mi][j][h*2 + 1];
                    if (Base) {
                        float2 bs = *(const float2*)(Base + o);
                        v.x = fmaf(beta, bs.x, v.x);
                        v.y = fmaf(beta, bs.y, v.y);
                    }
                    *(float2*)(Out + o) = v;
                }
            }
        }
    }
}

// ---------------------------------------------------------------------------
// Kernel 3: gate combine
// ---------------------------------------------------------------------------
__global__ void combine_gate(const float* __restrict__ X,
                             const float* __restrict__ T0,
                             const float* __restrict__ T1,
                             const float* __restrict__ T2,
                             const float* __restrict__ T3,
                             const float* __restrict__ gate_w,
                             const float* __restrict__ gate_b,
                             const float* __restrict__ xt,
                             const float* __restrict__ s1,
                             const float* __restrict__ s2,
                             float* __restrict__ cand,
                             float* __restrict__ r_out)
{
    __shared__ float s[8][DBASIS];
    const int t  = threadIdx.x;
    const int nb = blockIdx.x * 8;

    for (int idx = t; idx < 8*DBASIS; idx += 96) {
        int n = idx / DBASIS, i = idx - n*DBASIS;
        int term = i / DCAT, w = i - term*DCAT;
        const float* src;
        switch (term) {
            case 0: src = X;  break;
            case 1: src = T0; break;
            case 2: src = T1; break;
            case 3: src = X;  break;
            case 4: src = T2; break;
            default: src = T3; break;
        }
        s[n][i] = src[(size_t)(nb+n)*DCAT + w];
    }
    __syncthreads();

    const int c = t;
    float acc[8];
    float bc = gate_b[c];
#pragma unroll
    for (int n = 0; n < 8; n++) acc[n] = bc;

    for (int i = 0; i < DBASIS; i++) {
        float w = gate_w[i*GOUT + c];
#pragma unroll
        for (int n = 0; n < 8; n++)
            acc[n] = fmaf(s[n][i], w, acc[n]);
    }

#pragma unroll
    for (int n = 0; n < 8; n++) {
        int node = nb + n;
        float v = sigmoidf_(acc[n]);
        if (c < DO) {
            cand[(size_t)node*DCAT + DIN + c] = v * s1[node*DS + c];
        } else if (c < 2*DO) {
            int cc = c - DO;
            cand[(size_t)node*DCAT + DIN + DS + cc] = v * s2[node*DS + cc];
        } else {
            r_out[node*DO + (c - 2*DO)] = v;
        }
        if (c < DIN)
            cand[(size_t)node*DCAT + c] = xt[node*DIN + c];
    }
}

// ---------------------------------------------------------------------------
// Kernel 4: final
// ---------------------------------------------------------------------------
__global__ void final_kernel(const float* __restrict__ C,
                             const float* __restrict__ T0,
                             const float* __restrict__ T1,
                             const float* __restrict__ T2,
                             const float* __restrict__ T3,
                             const float* __restrict__ upd_w,
                             const float* __restrict__ upd_b,
                             const float* __restrict__ hop_w,
                             const float* __restrict__ hop_b,
                             const float* __restrict__ g_r,
                             const float* __restrict__ g_state,
                             float* __restrict__ out)
{
    __shared__ float s[8][DBASIS];
    __shared__ float hsh[8][DO];
    const int t  = threadIdx.x;
    const int nb = blockIdx.x * 8;

    for (int idx = t; idx < 8*DBASIS; idx += 256) {
        int n = idx / DBASIS, i = idx - n*DBASIS;
        int term = i / DCAT, w = i - term*DCAT;
        const float* src;
        switch (term) {
            case 0: src = C;  break;
            case 1: src = T0; break;
            case 2: src = T1; break;
            case 3: src = C;  break;
            case 4: src = T2; break;
            default: src = T3; break;
        }
        s[n][i] = src[(size_t)(nb+n)*DCAT + w];
    }
    __syncthreads();

    const int n = t >> 5;
    const int c = t & 31;
    const int node = nb + n;

    float acc = upd_b[c];
    for (int i = 0; i < DBASIS; i++)
        acc = fmaf(s[n][i], upd_w[i*DO + c], acc);

    float hc = tanhf(acc);
    float r  = g_r[node*DO + c];
    float st = g_state[node*DS + c];
    float h  = r*st + (1.0f - r)*hc;

    out[(size_t)node*DO + c] = h;
    hsh[n][c] = h;
    __syncthreads();

    float a2 = hop_b[c];
#pragma unroll
    for (int i = 0; i < HID; i++)
        a2 = fmaf(hsh[n][i], hop_w[i*HID + c], a2);
    out[(size_t)TOTN*DO + (size_t)node*HID + c] = a2;
}

// ---------------------------------------------------------------------------
// launch
// ---------------------------------------------------------------------------
extern "C" void kernel_launch(void* const* d_in, const int* in_sizes, int n_in,
                              void* d_out, int out_size)
{
    const float* xt     = (const float*)d_in[0];
    const float* s1     = (const float*)d_in[1];
    const float* s2     = (const float*)d_in[2];
    const float* ge     = (const float*)d_in[3];
    const float* sup    = (const float*)d_in[4];
    const float* mlp_w  = (const float*)d_in[5];
    const float* mlp_b  = (const float*)d_in[6];
    const float* gate_w = (const float*)d_in[7];
    const float* gate_b = (const float*)d_in[8];
    const float* upd_w  = (const float*)d_in[9];
    const float* upd_b  = (const float*)d_in[10];
    const float* hop_w  = (const float*)d_in[11];
    const float* hop_b  = (const float*)d_in[12];
    float* out = (float*)d_out;

    float* scr = nullptr;
    cudaGetSymbolAddress((void**)&scr, g_scratch);

    float* gX  = scr + OFF_X;
    float* gC  = scr + OFF_C;
    float* gT0 = scr + OFF_T0;
    float* gT1 = scr + OFF_T1;
    float* gT2 = scr + OFF_T2;
    float* gT3 = scr + OFF_T3;
    float* gST = scr + OFF_ST;
    float* gR  = scr + OFF_R;

    const float* A0 = sup;
    const float* A1 = sup + (size_t)BB * NN * NN;

    dim3 ggrid(NN / 64, BB);

    prep_kernel<<<TOTN/8, 256>>>(xt, s1, s2, ge, mlp_w, mlp_b, gX, gST);

    gemm_tc<<<ggrid, 128>>>(A0, gX,  nullptr, gT0, 1.0f,  0.0f);
    gemm_tc<<<ggrid, 128>>>(A0, gT0, gX,      gT1, 2.0f, -1.0f);
    gemm_tc<<<ggrid, 128>>>(A1, gX,  nullptr, gT2, 1.0f,  0.0f);
    gemm_tc<<<ggrid, 128>>>(A1, gT2, gX,      gT3, 2.0f, -1.0f);

    combine_gate<<<TOTN/8, 96>>>(gX, gT0, gT1, gT2, gT3,
                                 gate_w, gate_b, xt, s1, s2, gC, gR);

    gemm_tc<<<ggrid, 128>>>(A0, gC,  nullptr, gT0, 1.0f,  0.0f);
    gemm_tc<<<ggrid, 128>>>(A0, gT0, gC,      gT1, 2.0f, -1.0f);
    gemm_tc<<<ggrid, 128>>>(A1, gC,  nullptr, gT2, 1.0f,  0.0f);
    gemm_tc<<<ggrid, 128>>>(A1, gT2, gC,      gT3, 2.0f, -1.0f);

    final_kernel<<<TOTN/8, 256>>>(gC, gT0, gT1, gT2, gT3,
                                  upd_w, upd_b, hop_w, hop_b,
                                  gR, gST, out);
}